// round 1
// baseline (speedup 1.0000x reference)
#include <cuda_runtime.h>

// Problem constants
#define BS      64
#define NKP     17
#define A       8400
#define GRIDSZ  80            // IMAGE_SIZE / stride = 640/8
#define CH      (3*NKP)       // 51 channels
#define ROWLEN  A
#define BATCHSZ (CH*A)        // 428400 floats per batch
#define NROWS   (BS*NKP)      // 1088 conf rows
#define V4ROW   (A/4)         // 2100 float4 per row
#define TPB     256
#define BLKX    ((V4ROW + TPB - 1)/TPB)   // 9 blocks per row
#define NTOTAL  9139200.0f    // 64*17*8400

__device__ float g_acc[3];   // [0]=sum log1mp (all), [1]=sum (logp-log1mp) at vis positions, [2]=sum xy sq err

__global__ void k_init() {
    g_acc[0] = 0.f; g_acc[1] = 0.f; g_acc[2] = 0.f;
}

__global__ __launch_bounds__(TPB) void k_main(
    const float* __restrict__ out,
    const float* __restrict__ gtk,
    const int*   __restrict__ vis)
{
    // ---- dense part: row = (b,k), sum max(log(1-conf), -100) over A ----
    const int row = blockIdx.y;                 // 0..1087
    const int b = row / NKP;
    const int k = row - b * NKP;
    const int base = b * BATCHSZ + (3*k + 2) * ROWLEN;   // conf row
    const int col = blockIdx.x * TPB + threadIdx.x;

    float partial = 0.f;
    if (col < V4ROW) {
        float4 c = ((const float4*)(out + base))[col];
        partial  = fmaxf(__logf(1.0f - c.x), -100.f);
        partial += fmaxf(__logf(1.0f - c.y), -100.f);
        partial += fmaxf(__logf(1.0f - c.z), -100.f);
        partial += fmaxf(__logf(1.0f - c.w), -100.f);
    }

    // ---- sparse part: first 1088 global threads handle one (b,k) each ----
    const int flat = (blockIdx.y * gridDim.x + blockIdx.x) * TPB + threadIdx.x;
    if (flat < NROWS) {
        const int gb = flat / NKP;
        const int gk = flat - gb * NKP;
        const float gx = gtk[flat * 2 + 0];
        const float gy = gtk[flat * 2 + 1];
        if (vis[flat] == 1) {
            const int bx = (int)floorf(gx * 0.125f);
            const int by = (int)floorf(gy * 0.125f);
            const int idx = by * GRIDSZ + bx;
            const int rb = gb * BATCHSZ + 3 * gk * ROWLEN;
            const float xg = out[rb + idx];
            const float yg = out[rb + ROWLEN + idx];
            const float cg = out[rb + 2*ROWLEN + idx];
            const float dx = xg - gx, dy = yg - gy;
            atomicAdd(&g_acc[2], dx*dx + dy*dy);
            const float corr = fmaxf(__logf(cg), -100.f) - fmaxf(__logf(1.0f - cg), -100.f);
            atomicAdd(&g_acc[1], corr);
        }
    }

    // ---- block reduction of the dense partial ----
    #pragma unroll
    for (int o = 16; o > 0; o >>= 1)
        partial += __shfl_down_sync(0xffffffffu, partial, o);

    __shared__ float sh[TPB/32];
    if ((threadIdx.x & 31) == 0) sh[threadIdx.x >> 5] = partial;
    __syncthreads();
    if (threadIdx.x < TPB/32) {
        float v = sh[threadIdx.x];
        #pragma unroll
        for (int o = (TPB/64); o > 0; o >>= 1)
            v += __shfl_down_sync(0xffu, v, o);
        if (threadIdx.x == 0)
            atomicAdd(&g_acc[0], v);
    }
}

__global__ void k_final(float* __restrict__ res) {
    // conf_loss = -(sum_all log1mp + vis corrections) / N ; xy loss = sum / BS
    res[0] = -(g_acc[0] + g_acc[1]) / NTOTAL + g_acc[2] * (1.0f / (float)BS);
}

extern "C" void kernel_launch(void* const* d_in, const int* in_sizes, int n_in,
                              void* d_out, int out_size) {
    const float* out_t = (const float*)d_in[0];   // (64, 51, 8400) f32
    // d_in[1] = target (unused)
    const float* gtk   = (const float*)d_in[2];   // (64, 17, 2) f32
    const int*   vis   = (const int*)  d_in[3];   // (64, 17) i32
    float* res = (float*)d_out;

    k_init<<<1, 1>>>();
    dim3 grid(BLKX, NROWS);
    k_main<<<grid, TPB>>>(out_t, gtk, vis);
    k_final<<<1, 1>>>(res);
}

// round 2
// speedup vs baseline: 1.9550x; 1.9550x over previous
#include <cuda_runtime.h>

#define BS      64
#define NKP     17
#define A       8400
#define GRIDSZ  80             // 640 / stride(8)
#define CH      (3*NKP)        // 51
#define ROWLEN  A
#define BATCHSZ (CH*A)         // 428400 floats / batch
#define NROWS   (BS*NKP)       // 1088 conf rows
#define V4ROW   (A/4)          // 2100 float4 / row
#define TPB     256
#define NTOTAL  9139200.0f     // 64*17*8400
#define LN2F    0.69314718056f
#define L2CLAMP (-144.26950409f)   // -100 / ln2

__device__ float        g_acc[3];   // [0] dense sum log2(1-c), [1] vis corr (log2), [2] xy sqerr
__device__ unsigned int g_cnt;      // completed-block counter (zero-init, self-resetting)

__global__ __launch_bounds__(TPB) void k_fused(
    const float* __restrict__ out,
    const float* __restrict__ gtk,
    const int*   __restrict__ vis,
    float*       __restrict__ res)
{
    const int row = blockIdx.x;                 // 0..1087 == (b,k) flat
    const int b   = row / NKP;
    const int k   = row - b * NKP;
    const float4* p = (const float4*)(out + b * BATCHSZ + (3*k + 2) * ROWLEN);

    // ---- dense: sum max(log2(1-c), -100/ln2) over this row ----
    float s = 0.f;
    #pragma unroll
    for (int i = 0; i < 9; i++) {
        const int col = i * TPB + threadIdx.x;
        if (col < V4ROW) {
            const float4 c = p[col];
            s += fmaxf(__log2f(1.0f - c.x), L2CLAMP);
            s += fmaxf(__log2f(1.0f - c.y), L2CLAMP);
            s += fmaxf(__log2f(1.0f - c.z), L2CLAMP);
            s += fmaxf(__log2f(1.0f - c.w), L2CLAMP);
        }
    }

    // ---- sparse: this block's (b,k) gather, one lane ----
    if (threadIdx.x == TPB - 1) {               // last warp: keeps warp 0 free for reduce path
        const float gx = gtk[2*row], gy = gtk[2*row + 1];
        if (vis[row] == 1) {
            const int idx = (int)(gy * 0.125f) * GRIDSZ + (int)(gx * 0.125f);
            const float* rb = out + b * BATCHSZ + 3 * k * ROWLEN;
            const float xg = rb[idx];
            const float yg = rb[ROWLEN + idx];
            const float cg = rb[2*ROWLEN + idx];
            const float dx = xg - gx, dy = yg - gy;
            atomicAdd(&g_acc[2], dx*dx + dy*dy);
            atomicAdd(&g_acc[1], fmaxf(__log2f(cg), L2CLAMP)
                               - fmaxf(__log2f(1.0f - cg), L2CLAMP));
        }
    }

    // ---- block reduction ----
    #pragma unroll
    for (int o = 16; o > 0; o >>= 1)
        s += __shfl_down_sync(0xffffffffu, s, o);

    __shared__ float sh[TPB/32];
    if ((threadIdx.x & 31) == 0) sh[threadIdx.x >> 5] = s;
    __syncthreads();

    if (threadIdx.x == 0) {
        float v = 0.f;
        #pragma unroll
        for (int w = 0; w < TPB/32; w++) v += sh[w];
        atomicAdd(&g_acc[0], v);

        // ---- last-block finalize + self-reset (graph-replay deterministic) ----
        __threadfence();
        const unsigned int ticket = atomicAdd(&g_cnt, 1u);
        if (ticket == (unsigned)(gridDim.x - 1)) {
            __threadfence();
            const float a0 = *(volatile float*)&g_acc[0];
            const float a1 = *(volatile float*)&g_acc[1];
            const float a2 = *(volatile float*)&g_acc[2];
            res[0] = -(a0 + a1) * (LN2F / NTOTAL) + a2 * (1.0f / (float)BS);
            // reset for next replay
            *(volatile float*)&g_acc[0] = 0.f;
            *(volatile float*)&g_acc[1] = 0.f;
            *(volatile float*)&g_acc[2] = 0.f;
            *(volatile unsigned int*)&g_cnt = 0u;
        }
    }
}

extern "C" void kernel_launch(void* const* d_in, const int* in_sizes, int n_in,
                              void* d_out, int out_size) {
    const float* out_t = (const float*)d_in[0];   // (64, 51, 8400) f32
    const float* gtk   = (const float*)d_in[2];   // (64, 17, 2) f32
    const int*   vis   = (const int*)  d_in[3];   // (64, 17) i32
    float* res = (float*)d_out;

    k_fused<<<NROWS, TPB>>>(out_t, gtk, vis, res);
}